// round 8
// baseline (speedup 1.0000x reference)
#include <cuda_runtime.h>
#include <cstdint>

#define N_NODES 50000
#define N_EDGES_MAX 1600000
#define D 128
#define EPS 0.001f
#define SCAN_BLOCKS ((N_NODES + 1023) / 1024 + 1)

// Scratch (allocation-free rule: __device__ globals)
__device__ int g_degcnt[N_NODES];
__device__ int g_off[N_NODES + 1];
__device__ int g_cur[N_NODES];
__device__ int g_csrc[N_EDGES_MAX];
__device__ int g_bsum[SCAN_BLOCKS];
__device__ int g_is64;

// Packed f32x2 FMA (family-common on sm_100+; FFMA2 in SASS, PTX-only path)
__device__ __forceinline__ void ffma2(unsigned long long& d,
                                      unsigned long long a,
                                      unsigned long long b) {
    asm("fma.rn.f32x2 %0, %1, %2, %0;" : "+l"(d) : "l"(a), "l"(b));
}
__device__ __forceinline__ unsigned long long pack_dup(float v) {
    unsigned long long p;
    asm("mov.b64 %0, {%1, %1};" : "=l"(p) : "r"(__float_as_uint(v)));
    return p;
}
__device__ __forceinline__ void unpack2(unsigned long long p, float& lo, float& hi) {
    uint32_t a, b;
    asm("mov.b64 {%0, %1}, %2;" : "=r"(a), "=r"(b) : "l"(p));
    lo = __uint_as_float(a);
    hi = __uint_as_float(b);
}

// ===========================================================================
// CSR build (unchanged — validated)
// ===========================================================================
__global__ void detect_kernel(const int* __restrict__ e32) {
    if (threadIdx.x == 0 && blockIdx.x == 0) {
        int is64 = 1;
        #pragma unroll 1
        for (int k = 1; k < 128; k += 2) {
            if (e32[k] != 0) { is64 = 0; break; }
        }
        g_is64 = is64;
    }
}

__global__ void zero_deg_kernel(int* __restrict__ degcnt, int n) {
    int i = blockIdx.x * blockDim.x + threadIdx.x;
    if (i < n) degcnt[i] = 0;
}

__global__ void hist_kernel(const void* __restrict__ ei, int E,
                            int* __restrict__ degcnt) {
    int i = blockIdx.x * blockDim.x + threadIdx.x;
    if (i >= E) return;
    int dd;
    if (g_is64) dd = (int)reinterpret_cast<const long long*>(ei)[(size_t)E + i];
    else        dd = reinterpret_cast<const int*>(ei)[(size_t)E + i];
    atomicAdd(degcnt + dd, 1);
}

__global__ void scan_part_kernel(const int* __restrict__ degcnt,
                                 int* __restrict__ off,
                                 int* __restrict__ bsum, int N) {
    __shared__ int wsum[32];
    const int tid = threadIdx.x, lane = tid & 31, wid = tid >> 5;
    int idx = blockIdx.x * 1024 + tid;
    int v = (idx < N) ? degcnt[idx] : 0;
    int incl = v;
    #pragma unroll
    for (int o = 1; o < 32; o <<= 1) {
        int t = __shfl_up_sync(0xffffffffu, incl, o);
        if (lane >= o) incl += t;
    }
    if (lane == 31) wsum[wid] = incl;
    __syncthreads();
    if (wid == 0) {
        int s = wsum[lane];
        #pragma unroll
        for (int o = 1; o < 32; o <<= 1) {
            int t = __shfl_up_sync(0xffffffffu, s, o);
            if (lane >= o) s += t;
        }
        wsum[lane] = s;
    }
    __syncthreads();
    int woff = wid ? wsum[wid - 1] : 0;
    if (idx < N) off[idx] = woff + incl - v;
    if (tid == 1023) bsum[blockIdx.x] = woff + incl;
}

__global__ void scan_tops_kernel(int* __restrict__ bsum, int nb) {
    const int tid = threadIdx.x, lane = tid & 31;
    int v = (tid < nb) ? bsum[tid] : 0;
    int incl = v;
    #pragma unroll
    for (int o = 1; o < 32; o <<= 1) {
        int t = __shfl_up_sync(0xffffffffu, incl, o);
        if (lane >= o) incl += t;
    }
    __shared__ int w0_total;
    if (tid == 31) w0_total = incl;
    __syncthreads();
    int base = (tid >= 32) ? w0_total : 0;
    if (tid < nb) bsum[tid] = base + incl - v;
    if (tid == nb - 1) bsum[nb] = base + incl;
}

__global__ void scan_add_kernel(int* __restrict__ off, int* __restrict__ cur,
                                const int* __restrict__ bsum, int N, int nb) {
    int idx = blockIdx.x * 1024 + threadIdx.x;
    if (idx < N) {
        int v = off[idx] + bsum[blockIdx.x];
        off[idx] = v;
        cur[idx] = v;
    }
    if (idx == 0) off[N] = bsum[nb];
}

__global__ void fill_kernel(const void* __restrict__ ei, int E,
                            int* __restrict__ cur, int* __restrict__ csrc) {
    int i = blockIdx.x * blockDim.x + threadIdx.x;
    if (i >= E) return;
    int ss, dd;
    if (g_is64) {
        const long long* e = reinterpret_cast<const long long*>(ei);
        ss = (int)e[i];
        dd = (int)e[(size_t)E + i];
    } else {
        const int* e = reinterpret_cast<const int*>(ei);
        ss = e[i];
        dd = e[(size_t)E + i];
    }
    int pos = atomicAdd(cur + dd, 1);
    csrc[pos] = ss;
}

// ===========================================================================
// Fully fused GIN layer: per 128-row tile CTA (256 threads):
//   Phase A: aggregate h = (1+eps)x + sum_neighbors x  directly into SMEM
//   Phase B: GEMM1 (FFMA2) + bias/relu -> overwrite Hs
//   Phase C: GEMM2 (FFMA2) + bias -> out
// Cross-CTA overlap of L2-bound Phase A with FMA-bound Phases B/C.
// ===========================================================================
__global__ void __launch_bounds__(256, 2)
gin_fused_kernel(const float* __restrict__ x,
                 const int* __restrict__ csrc,
                 const int* __restrict__ off,
                 const float* __restrict__ W1, const float* __restrict__ b1,
                 const float* __restrict__ W2, const float* __restrict__ b2,
                 float* __restrict__ out, int M) {
    extern __shared__ float sm[];
    float* Hs = sm;                    // [128][132] h tile, then h1 tile
    float* Bs = Hs + 128 * 132;        // [16][128] weight chunk

    const int tid = threadIdx.x;
    const int wid = tid >> 5;
    const int lane = tid & 31;
    const int row_base = blockIdx.x * 128;

    // ---------------- Phase A: aggregation into Hs ----------------
    #pragma unroll 1
    for (int t = 0; t < 16; t++) {
        const int lrow = wid * 16 + t;          // 0..127
        const int node = row_base + lrow;
        float4 acc = make_float4(0.f, 0.f, 0.f, 0.f);
        if (node < M) {
            acc = *reinterpret_cast<const float4*>(x + (size_t)node * D + lane * 4);
            const float sc = 1.0f + EPS;
            acc.x *= sc; acc.y *= sc; acc.z *= sc; acc.w *= sc;
            int j = off[node];
            const int e = off[node + 1];
            for (; j + 4 <= e; j += 4) {
                int a0 = __ldg(csrc + j),     a1 = __ldg(csrc + j + 1);
                int a2 = __ldg(csrc + j + 2), a3 = __ldg(csrc + j + 3);
                float4 v0 = *reinterpret_cast<const float4*>(x + (size_t)a0 * D + lane * 4);
                float4 v1 = *reinterpret_cast<const float4*>(x + (size_t)a1 * D + lane * 4);
                float4 v2 = *reinterpret_cast<const float4*>(x + (size_t)a2 * D + lane * 4);
                float4 v3 = *reinterpret_cast<const float4*>(x + (size_t)a3 * D + lane * 4);
                acc.x += (v0.x + v1.x) + (v2.x + v3.x);
                acc.y += (v0.y + v1.y) + (v2.y + v3.y);
                acc.z += (v0.z + v1.z) + (v2.z + v3.z);
                acc.w += (v0.w + v1.w) + (v2.w + v3.w);
            }
            for (; j < e; j++) {
                int a0 = __ldg(csrc + j);
                float4 v0 = *reinterpret_cast<const float4*>(x + (size_t)a0 * D + lane * 4);
                acc.x += v0.x; acc.y += v0.y; acc.z += v0.z; acc.w += v0.w;
            }
        }
        *reinterpret_cast<float4*>(Hs + lrow * 132 + lane * 4) = acc;
    }
    __syncthreads();

    // ---------------- Phase B: GEMM1 = Hs @ W1, relu+bias -> Hs ----------------
    const int tx = tid & 15;
    const int ty = tid >> 4;
    const int col0 = tx * 8;

    unsigned long long acc[8][4];
    #pragma unroll
    for (int i = 0; i < 8; i++)
        #pragma unroll
        for (int j = 0; j < 4; j++) acc[i][j] = 0ull;

    for (int kk = 0; kk < 128; kk += 16) {
        #pragma unroll
        for (int i = 0; i < 2; i++) {
            int f = tid * 2 + i;
            int kb = f >> 5;
            int n4 = f & 31;
            *reinterpret_cast<float4*>(Bs + kb * 128 + n4 * 4) =
                *reinterpret_cast<const float4*>(W1 + (size_t)(kk + kb) * D + n4 * 4);
        }
        __syncthreads();

        #pragma unroll
        for (int k = 0; k < 16; k++) {
            const unsigned long long* bp =
                reinterpret_cast<const unsigned long long*>(Bs + k * 128 + col0);
            unsigned long long bv0 = bp[0], bv1 = bp[1], bv2 = bp[2], bv3 = bp[3];
            #pragma unroll
            for (int i = 0; i < 8; i++) {
                unsigned long long ap = pack_dup(Hs[(ty * 8 + i) * 132 + kk + k]);
                ffma2(acc[i][0], ap, bv0);
                ffma2(acc[i][1], ap, bv1);
                ffma2(acc[i][2], ap, bv2);
                ffma2(acc[i][3], ap, bv3);
            }
        }
        __syncthreads();
    }

    {
        float bv[8];
        #pragma unroll
        for (int j = 0; j < 8; j++) bv[j] = b1[col0 + j];
        #pragma unroll
        for (int i = 0; i < 8; i++) {
            int row = ty * 8 + i;
            float o[8];
            #pragma unroll
            for (int j = 0; j < 4; j++) {
                unpack2(acc[i][j], o[2 * j], o[2 * j + 1]);
                acc[i][j] = 0ull;
            }
            float4 o0, o1;
            o0.x = fmaxf(o[0] + bv[0], 0.f);
            o0.y = fmaxf(o[1] + bv[1], 0.f);
            o0.z = fmaxf(o[2] + bv[2], 0.f);
            o0.w = fmaxf(o[3] + bv[3], 0.f);
            o1.x = fmaxf(o[4] + bv[4], 0.f);
            o1.y = fmaxf(o[5] + bv[5], 0.f);
            o1.z = fmaxf(o[6] + bv[6], 0.f);
            o1.w = fmaxf(o[7] + bv[7], 0.f);
            // Safe: all GEMM1 reads of Hs completed before the trailing
            // __syncthreads of the last kk chunk.
            *reinterpret_cast<float4*>(Hs + row * 132 + col0)     = o0;
            *reinterpret_cast<float4*>(Hs + row * 132 + col0 + 4) = o1;
        }
    }
    __syncthreads();

    // ---------------- Phase C: GEMM2 = Hs @ W2, bias -> out ----------------
    for (int kk = 0; kk < 128; kk += 16) {
        #pragma unroll
        for (int i = 0; i < 2; i++) {
            int f = tid * 2 + i;
            int kb = f >> 5;
            int n4 = f & 31;
            *reinterpret_cast<float4*>(Bs + kb * 128 + n4 * 4) =
                *reinterpret_cast<const float4*>(W2 + (size_t)(kk + kb) * D + n4 * 4);
        }
        __syncthreads();

        #pragma unroll
        for (int k = 0; k < 16; k++) {
            const unsigned long long* bp =
                reinterpret_cast<const unsigned long long*>(Bs + k * 128 + col0);
            unsigned long long bv0 = bp[0], bv1 = bp[1], bv2 = bp[2], bv3 = bp[3];
            #pragma unroll
            for (int i = 0; i < 8; i++) {
                unsigned long long ap = pack_dup(Hs[(ty * 8 + i) * 132 + kk + k]);
                ffma2(acc[i][0], ap, bv0);
                ffma2(acc[i][1], ap, bv1);
                ffma2(acc[i][2], ap, bv2);
                ffma2(acc[i][3], ap, bv3);
            }
        }
        __syncthreads();
    }

    {
        float bv[8];
        #pragma unroll
        for (int j = 0; j < 8; j++) bv[j] = b2[col0 + j];
        #pragma unroll
        for (int i = 0; i < 8; i++) {
            int r = row_base + ty * 8 + i;
            if (r < M) {
                float o[8];
                #pragma unroll
                for (int j = 0; j < 4; j++)
                    unpack2(acc[i][j], o[2 * j], o[2 * j + 1]);
                float4 o0, o1;
                o0.x = o[0] + bv[0];
                o0.y = o[1] + bv[1];
                o0.z = o[2] + bv[2];
                o0.w = o[3] + bv[3];
                o1.x = o[4] + bv[4];
                o1.y = o[5] + bv[5];
                o1.z = o[6] + bv[6];
                o1.w = o[7] + bv[7];
                *reinterpret_cast<float4*>(out + (size_t)r * D + col0)     = o0;
                *reinterpret_cast<float4*>(out + (size_t)r * D + col0 + 4) = o1;
            }
        }
    }
}

extern "C" void kernel_launch(void* const* d_in, const int* in_sizes, int n_in,
                              void* d_out, int out_size) {
    const float* x  = (const float*)d_in[0];
    const void*  ei = d_in[1];
    const float* W1 = (const float*)d_in[2];
    const float* b1 = (const float*)d_in[3];
    const float* W2 = (const float*)d_in[4];
    const float* b2 = (const float*)d_in[5];
    float* out = (float*)d_out;

    const int N = in_sizes[0] / D;
    const int E = in_sizes[1] / 2;
    const int nb = (N + 1023) / 1024;

    int* p_deg  = nullptr;
    int* p_off  = nullptr;
    int* p_cur  = nullptr;
    int* p_csrc = nullptr;
    int* p_bsum = nullptr;
    cudaGetSymbolAddress((void**)(&p_deg),  g_degcnt);
    cudaGetSymbolAddress((void**)(&p_off),  g_off);
    cudaGetSymbolAddress((void**)(&p_cur),  g_cur);
    cudaGetSymbolAddress((void**)(&p_csrc), g_csrc);
    cudaGetSymbolAddress((void**)(&p_bsum), g_bsum);

    const int smem_fused = (128 * 132 + 16 * 128) * (int)sizeof(float);
    static int attr_set = 0;
    if (!attr_set) {
        cudaFuncSetAttribute(gin_fused_kernel,
                             cudaFuncAttributeMaxDynamicSharedMemorySize,
                             smem_fused);
        attr_set = 1;
    }

    detect_kernel<<<1, 32>>>((const int*)ei);

    zero_deg_kernel<<<(N + 255) / 256, 256>>>(p_deg, N);
    hist_kernel<<<(E + 255) / 256, 256>>>(ei, E, p_deg);
    scan_part_kernel<<<nb, 1024>>>(p_deg, p_off, p_bsum, N);
    scan_tops_kernel<<<1, 64>>>(p_bsum, nb);
    scan_add_kernel<<<nb, 1024>>>(p_off, p_cur, p_bsum, N, nb);
    fill_kernel<<<(E + 255) / 256, 256>>>(ei, E, p_cur, p_csrc);

    int gblocks = (N + 127) / 128;
    gin_fused_kernel<<<gblocks, 256, smem_fused>>>(x, p_csrc, p_off,
                                                   W1, b1, W2, b2, out, N);
}